// round 17
// baseline (speedup 1.0000x reference)
#include <cuda_runtime.h>
#include <cuda_bf16.h>

// Problem constants
#define R_REL 8
#define C_CH  4
#define E_EDG 2000000u
#define RE    (R_REL * E_EDG)          // 16,000,000
#define T_TILE 2000u                   // edges per tile (divides E exactly)
#define TILES_PER_R (E_EDG / T_TILE)   // 1000
#define T_VEC (T_TILE / 4u)            // 500 float4 per stream segment

// ---------------------------------------------------------------------------
// Smem-staged, stream-serialized variant (alignment-fixed).
// Phase 1: block cooperatively stages one 2000-edge tile (index rows converted
//          to float + edge_value) into shared memory. Only 3 read streams.
// Phase 2: the 6 output streams are written ONE AT A TIME, whole-block
//          contiguous (8 KB burst per stream), maximizing per-stream DRAM
//          row locality instead of interleaving 9 streams per warp.
// Output layout (float32):
//   [0*RE .. 1*RE)  : (float)edge_index[r, 0, e]  at slot r*E+e
//   [1*RE .. 2*RE)  : (float)edge_index[r, 1, e]
//   [2*RE + c*RE)   : filt[r][c] * edge_value[r, e],  c = 0..3
// ---------------------------------------------------------------------------
__global__ void __launch_bounds__(256) gtconv_staged_kernel(
    const float* __restrict__ weight,
    const void*  __restrict__ edge_index_raw,
    const float* __restrict__ edge_value,
    float* __restrict__ out)
{
    __shared__ float s_filt[R_REL * C_CH];
    __shared__ int   s_is64;
    __shared__ __align__(16) float s_i0[T_TILE];
    __shared__ __align__(16) float s_i1[T_TILE];
    __shared__ __align__(16) float s_v [T_TILE];

    unsigned t = threadIdx.x;
    if (t < C_CH) {
        float v[R_REL];
        float m = -1e30f;
        #pragma unroll
        for (int r = 0; r < R_REL; r++) {
            v[r] = __ldg(&weight[r * C_CH + t]);
            m = fmaxf(m, v[r]);
        }
        float s = 0.f;
        #pragma unroll
        for (int r = 0; r < R_REL; r++) {
            v[r] = __expf(v[r] - m);
            s += v[r];
        }
        float inv = 1.f / s;
        #pragma unroll
        for (int r = 0; r < R_REL; r++)
            s_filt[r * C_CH + t] = v[r] * inv;
    } else if (t == 32) {
        const unsigned long long* q = (const unsigned long long*)edge_index_raw;
        int is64 = 1;
        #pragma unroll
        for (int i = 0; i < 16; i++)
            if ((__ldg(&q[i]) >> 32) != 0ULL) is64 = 0;
        s_is64 = is64;
    }
    __syncthreads();

    unsigned tile = blockIdx.x;               // 0 .. 7999
    unsigned r    = tile / TILES_PER_R;       // 0..7
    unsigned t0   = (tile % TILES_PER_R) * T_TILE;
    unsigned base = r * E_EDG + t0;           // element offset in value/out streams

    // ---- Phase 1: stage tile into smem (3 read streams, converted) ----
    if (s_is64) {
        const long long* ei = (const long long*)edge_index_raw;
        const longlong2* p0 = reinterpret_cast<const longlong2*>(ei + (size_t)r * 2 * E_EDG + t0);
        const longlong2* p1 = reinterpret_cast<const longlong2*>(ei + (size_t)r * 2 * E_EDG + E_EDG + t0);
        for (unsigned u = t; u < T_TILE / 2; u += 256) {
            longlong2 a = __ldcs(&p0[u]);
            longlong2 b = __ldcs(&p1[u]);
            s_i0[2*u]   = (float)(int)a.x;  s_i0[2*u+1] = (float)(int)a.y;
            s_i1[2*u]   = (float)(int)b.x;  s_i1[2*u+1] = (float)(int)b.y;
        }
        const float4* pv = reinterpret_cast<const float4*>(edge_value + base);
        for (unsigned u = t; u < T_VEC; u += 256) {
            float4 v = __ldcs(&pv[u]);
            reinterpret_cast<float4*>(s_v)[u] = v;
        }
    } else {
        const int* ei = (const int*)edge_index_raw;
        const int4* p0 = reinterpret_cast<const int4*>(ei + (size_t)r * 2 * E_EDG + t0);
        const int4* p1 = reinterpret_cast<const int4*>(ei + (size_t)r * 2 * E_EDG + E_EDG + t0);
        const float4* pv = reinterpret_cast<const float4*>(edge_value + base);
        for (unsigned u = t; u < T_VEC; u += 256) {
            int4 a = __ldcs(&p0[u]);
            int4 b = __ldcs(&p1[u]);
            float4 v = __ldcs(&pv[u]);
            reinterpret_cast<float4*>(s_i0)[u] =
                make_float4((float)a.x, (float)a.y, (float)a.z, (float)a.w);
            reinterpret_cast<float4*>(s_i1)[u] =
                make_float4((float)b.x, (float)b.y, (float)b.z, (float)b.w);
            reinterpret_cast<float4*>(s_v)[u] = v;
        }
    }
    __syncthreads();

    // ---- Phase 2: write 6 output streams serially, block-contiguous ----
    const float4 fc = *reinterpret_cast<const float4*>(&s_filt[r * C_CH]);
    const float  scales[6] = {1.f, 1.f, fc.x, fc.y, fc.z, fc.w};
    const float* srcs[6]   = {s_i0, s_i1, s_v, s_v, s_v, s_v};
    float*       dsts[6]   = {
        out + base,
        out + RE + base,
        out + 2u*RE + 0u*RE + base,
        out + 2u*RE + 1u*RE + base,
        out + 2u*RE + 2u*RE + base,
        out + 2u*RE + 3u*RE + base
    };

    #pragma unroll
    for (int s = 0; s < 6; s++) {
        const float4* sp = reinterpret_cast<const float4*>(srcs[s]);
        float4*       dp = reinterpret_cast<float4*>(dsts[s]);
        float         sc = scales[s];
        for (unsigned u = t; u < T_VEC; u += 256) {
            float4 x = sp[u];
            __stcs(&dp[u], make_float4(x.x * sc, x.y * sc, x.z * sc, x.w * sc));
        }
    }
}

extern "C" void kernel_launch(void* const* d_in, const int* in_sizes, int n_in,
                              void* d_out, int out_size) {
    const float* weight     = (const float*)d_in[0];
    const void*  edge_index = (const void*)d_in[1];
    const float* edge_value = (const float*)d_in[2];
    float* out = (float*)d_out;

    int threads = 256;
    int blocks  = (int)(R_REL * TILES_PER_R);   // 8000 tiles, exact cover
    gtconv_staged_kernel<<<blocks, threads>>>(weight, edge_index, edge_value, out);
}